// round 5
// baseline (speedup 1.0000x reference)
#include <cuda_runtime.h>
#include <cuda_bf16.h>
#include <cuda_fp16.h>
#include <math_constants.h>
#include <cstdint>

#define N_NODES 50000
#define N_EDGES 800000
#define HID 128
#define PW 384   // [0:128)=z@Ws, [128:256)=z@Wd, [256:384)=z@W1a
#define SCAN_BLOCKS ((N_NODES + 255) / 256)   // 196

// ---------------- scratch ----------------
__device__ float  g_P[(size_t)N_NODES * PW];
__device__ __half g_Ps16[(size_t)N_NODES * HID];   // fp16 copy of z@Ws for the edge gather
__device__ float  g_agg[(size_t)N_NODES * HID];
__device__ int    g_count[N_NODES];
__device__ int    g_offset[N_NODES];
__device__ int    g_cursor[N_NODES];
__device__ int    g_blocksum[SCAN_BLOCKS];
__device__ int    g_sorted_src[N_EDGES];
__device__ float  g_sorted_w[N_EDGES];

// ---------------- mma.sync helpers (portable sm_80+ PTX) ----------------
__device__ __forceinline__ uint32_t smem_u32(const void* p) {
    uint32_t a;
    asm("{ .reg .u64 t; cvta.to.shared.u64 t, %1; cvt.u32.u64 %0, t; }" : "=r"(a) : "l"(p));
    return a;
}
__device__ __forceinline__ void ldsm_x4(uint32_t* r, uint32_t addr) {
    asm volatile("ldmatrix.sync.aligned.m8n8.x4.shared.b16 {%0,%1,%2,%3}, [%4];"
                 : "=r"(r[0]), "=r"(r[1]), "=r"(r[2]), "=r"(r[3]) : "r"(addr));
}
__device__ __forceinline__ void ldsm_x4_t(uint32_t* r, uint32_t addr) {
    asm volatile("ldmatrix.sync.aligned.m8n8.x4.trans.shared.b16 {%0,%1,%2,%3}, [%4];"
                 : "=r"(r[0]), "=r"(r[1]), "=r"(r[2]), "=r"(r[3]) : "r"(addr));
}
__device__ __forceinline__ void mma16816(float* c, const uint32_t* a, const uint32_t* b) {
    asm volatile(
        "mma.sync.aligned.m16n8k16.row.col.f32.bf16.bf16.f32 "
        "{%0,%1,%2,%3}, {%4,%5,%6,%7}, {%8,%9}, {%0,%1,%2,%3};"
        : "+f"(c[0]), "+f"(c[1]), "+f"(c[2]), "+f"(c[3])
        : "r"(a[0]), "r"(a[1]), "r"(a[2]), "r"(a[3]), "r"(b[0]), "r"(b[1]));
}
__device__ __forceinline__ uint32_t pack2(float x, float y) {
    __nv_bfloat162 h = __floats2bfloat162_rn(x, y);
    return *(uint32_t*)&h;
}
__device__ __forceinline__ float tobf(float x) {
    return __bfloat162float(__float2bfloat16(x));
}
// swizzled byte offset inside a [128][128] bf16 tile (256B rows)
__device__ __forceinline__ uint32_t swz(int row, int col) {
    return (uint32_t)(row * 256 + ((((col >> 3) ^ (row & 7))) << 4) + (col & 7) * 2);
}

// smem offsets
#define SM_AHI 0
#define SM_ALO 32768
#define SM_BHI 65536
#define SM_BLO 98304
#define SM_Z_TOTAL 131072          // gemm_z: A + one B
#define SM_B2H 131072
#define SM_B2L 163840
#define SM_T_TOTAL 196608          // gemm_tail: A + B1 + B2

// ---- shared building blocks ----
__device__ __forceinline__ void conv_A(const float* __restrict__ A, int bm0, int M,
                                       char* smem, int offH, int offL, int tid) {
#pragma unroll
    for (int i = 0; i < 32; i++) {
        int p = tid + i * 256;
        int row = p >> 6, col = (p & 63) * 2;
        float2 v = make_float2(0.f, 0.f);
        int gr = bm0 + row;
        if (gr < M) v = *(const float2*)(A + (size_t)gr * 128 + col);
        float hx = tobf(v.x), hy = tobf(v.y);
        uint32_t off = swz(row, col);
        *(uint32_t*)(smem + offH + off) = pack2(hx, hy);
        *(uint32_t*)(smem + offL + off) = pack2(v.x - hx, v.y - hy);
    }
}
__device__ __forceinline__ void conv_B(const float* __restrict__ B,
                                       char* smem, int offH, int offL, int tid) {
#pragma unroll
    for (int i = 0; i < 32; i++) {
        int p = tid + i * 256;
        int row = p >> 6, col = (p & 63) * 2;
        float2 v = *(const float2*)(B + (size_t)row * 128 + col);
        float hx = tobf(v.x), hy = tobf(v.y);
        uint32_t off = swz(row, col);
        *(uint32_t*)(smem + offH + off) = pack2(hx, hy);
        *(uint32_t*)(smem + offL + off) = pack2(v.x - hx, v.y - hy);
    }
}
// split-bf16 MMA over full K=128: D = AH*BH + AH*BL + AL*BH
__device__ __forceinline__ void mma_stage(uint32_t sb, int aHo, int aLo, int bHo, int bLo,
                                          int wm, int wn, int lane, float (&acc)[4][4][4]) {
    const int sub = lane >> 3;
    const int l7 = lane & 7;
    const int radd = (sub & 1) * 8;
    const int cadd = (sub >> 1) * 8;
#pragma unroll
    for (int ks = 0; ks < 8; ks++) {
        const int k0 = ks * 16;
        uint32_t aH[4][4], aL[4][4], bH[2][4], bL[2][4];
#pragma unroll
        for (int mt = 0; mt < 4; mt++) {
            uint32_t o = swz(wm * 64 + mt * 16 + l7 + radd, k0 + cadd);
            ldsm_x4(aH[mt], sb + aHo + o);
            ldsm_x4(aL[mt], sb + aLo + o);
        }
#pragma unroll
        for (int pr = 0; pr < 2; pr++) {
            uint32_t o = swz(k0 + l7 + radd, wn * 32 + pr * 16 + cadd);
            ldsm_x4_t(bH[pr], sb + bHo + o);
            ldsm_x4_t(bL[pr], sb + bLo + o);
        }
#pragma unroll
        for (int mt = 0; mt < 4; mt++)
#pragma unroll
            for (int nt = 0; nt < 4; nt++) {
                const uint32_t* bh = &bH[nt >> 1][(nt & 1) * 2];
                const uint32_t* bl = &bL[nt >> 1][(nt & 1) * 2];
                mma16816(acc[mt][nt], aH[mt], bh);
                mma16816(acc[mt][nt], aH[mt], bl);
                mma16816(acc[mt][nt], aL[mt], bh);
            }
    }
}

// ---------------- GEMM 1: P = z @ [Ws | Wd | W1a], A converted once ----------------
__global__ __launch_bounds__(256)
void gemm_z_fused(const float* __restrict__ z, const float* __restrict__ Wm,
                  const float* __restrict__ W1, int M)
{
    extern __shared__ char smem[];
    const uint32_t sb = smem_u32(smem);
    const int tid = threadIdx.x;
    const int wid = tid >> 5;
    const int lane = tid & 31;
    const int bm0 = blockIdx.x * 128;
    const int wm = wid & 1, wn = wid >> 1;
    const int g = lane >> 2, tg = lane & 3;

    conv_A(z, bm0, M, smem, SM_AHI, SM_ALO, tid);

    const float* Bmats[3] = { Wm + 128 * 128, Wm, W1 };  // Ws, Wd, W1a
#pragma unroll 1
    for (int by = 0; by < 3; by++) {
        if (by) __syncthreads();          // protect B smem from prior readers
        conv_B(Bmats[by], smem, SM_BHI, SM_BLO, tid);
        __syncthreads();

        float acc[4][4][4];
#pragma unroll
        for (int mt = 0; mt < 4; mt++)
#pragma unroll
            for (int nt = 0; nt < 4; nt++)
#pragma unroll
                for (int j = 0; j < 4; j++) acc[mt][nt][j] = 0.f;

        mma_stage(sb, SM_AHI, SM_ALO, SM_BHI, SM_BLO, wm, wn, lane, acc);

        // epilogue -> g_P[:, by*128 ...] (+ fp16 table when by==0)
#pragma unroll
        for (int mt = 0; mt < 4; mt++)
#pragma unroll
            for (int half = 0; half < 2; half++) {
                int r = bm0 + wm * 64 + mt * 16 + g + half * 8;
                if (r >= M) continue;
                float* orow = g_P + (size_t)r * PW + by * 128;
#pragma unroll
                for (int nt = 0; nt < 4; nt++) {
                    int lc = wn * 32 + nt * 8 + 2 * tg;
                    float2 v;
                    v.x = acc[mt][nt][half * 2 + 0];
                    v.y = acc[mt][nt][half * 2 + 1];
                    *(float2*)(orow + lc) = v;
                    if (by == 0) {
                        __half2 h = __floats2half2_rn(v.x, v.y);
                        *(__half2*)(g_Ps16 + (size_t)r * HID + lc) = h;
                    }
                }
            }
    }
}

// ---------------- GEMM tail: out = relu(agg@W1b + P3 + b1) @ W2 + b2 ----------------
__global__ __launch_bounds__(256)
void gemm_tail(const float* __restrict__ W1b, const float* __restrict__ b1,
               const float* __restrict__ W2, const float* __restrict__ b2,
               float* __restrict__ out, int M)
{
    extern __shared__ char smem[];
    const uint32_t sb = smem_u32(smem);
    const int tid = threadIdx.x;
    const int wid = tid >> 5;
    const int lane = tid & 31;
    const int bm0 = blockIdx.x * 128;
    const int wm = wid & 1, wn = wid >> 1;
    const int g = lane >> 2, tg = lane & 3;

    conv_A(g_agg, bm0, M, smem, SM_AHI, SM_ALO, tid);
    conv_B(W1b, smem, SM_BHI, SM_BLO, tid);
    conv_B(W2,  smem, SM_B2H, SM_B2L, tid);
    __syncthreads();

    float acc[4][4][4];
#pragma unroll
    for (int mt = 0; mt < 4; mt++)
#pragma unroll
        for (int nt = 0; nt < 4; nt++)
#pragma unroll
            for (int j = 0; j < 4; j++) acc[mt][nt][j] = 0.f;

    mma_stage(sb, SM_AHI, SM_ALO, SM_BHI, SM_BLO, wm, wn, lane, acc);
    __syncthreads();   // everyone done reading A before we overwrite it with hidden

    // epilogue 1: hidden = relu(acc + b1 + P3) -> split bf16 back into A smem
#pragma unroll
    for (int mt = 0; mt < 4; mt++)
#pragma unroll
        for (int half = 0; half < 2; half++) {
            int lr = wm * 64 + mt * 16 + g + half * 8;
            int r = bm0 + lr;
            const float* crow = (r < M) ? (g_P + (size_t)r * PW + 256) : nullptr;
#pragma unroll
            for (int nt = 0; nt < 4; nt++) {
                int lc = wn * 32 + nt * 8 + 2 * tg;
                float2 v;
                v.x = acc[mt][nt][half * 2 + 0] + b1[lc];
                v.y = acc[mt][nt][half * 2 + 1] + b1[lc + 1];
                if (crow) { v.x += crow[lc]; v.y += crow[lc + 1]; }
                v.x = fmaxf(v.x, 0.f); v.y = fmaxf(v.y, 0.f);
                float hx = tobf(v.x), hy = tobf(v.y);
                uint32_t off = swz(lr, lc);
                *(uint32_t*)(smem + SM_AHI + off) = pack2(hx, hy);
                *(uint32_t*)(smem + SM_ALO + off) = pack2(v.x - hx, v.y - hy);
            }
        }
    __syncthreads();

#pragma unroll
    for (int mt = 0; mt < 4; mt++)
#pragma unroll
        for (int nt = 0; nt < 4; nt++)
#pragma unroll
            for (int j = 0; j < 4; j++) acc[mt][nt][j] = 0.f;

    mma_stage(sb, SM_AHI, SM_ALO, SM_B2H, SM_B2L, wm, wn, lane, acc);

    // epilogue 2 -> out
#pragma unroll
    for (int mt = 0; mt < 4; mt++)
#pragma unroll
        for (int half = 0; half < 2; half++) {
            int r = bm0 + wm * 64 + mt * 16 + g + half * 8;
            if (r >= M) continue;
            float* orow = out + (size_t)r * HID;
#pragma unroll
            for (int nt = 0; nt < 4; nt++) {
                int lc = wn * 32 + nt * 8 + 2 * tg;
                float2 v;
                v.x = acc[mt][nt][half * 2 + 0] + b2[lc];
                v.y = acc[mt][nt][half * 2 + 1] + b2[lc + 1];
                *(float2*)(orow + lc) = v;
            }
        }
}

// ---------------- edge counting sort ----------------
__global__ void zero_count_kernel() {
    int i = blockIdx.x * blockDim.x + threadIdx.x;
    if (i < N_NODES) g_count[i] = 0;
}
__global__ void hist_kernel(const int* __restrict__ edst) {
    int i = blockIdx.x * blockDim.x + threadIdx.x;
    if (i < N_EDGES) atomicAdd(&g_count[edst[i]], 1);
}
__global__ void scan_local() {
    int b = blockIdx.x, t = threadIdx.x;
    int i = b * 256 + t;
    int v = (i < N_NODES) ? g_count[i] : 0;
    int lane = t & 31, w = t >> 5;
    int incl = v;
#pragma unroll
    for (int o = 1; o < 32; o <<= 1) {
        int y = __shfl_up_sync(0xffffffffu, incl, o);
        if (lane >= o) incl += y;
    }
    __shared__ int ws[8];
    if (lane == 31) ws[w] = incl;
    __syncthreads();
    if (t < 8) {
        int x = ws[t];
#pragma unroll
        for (int o = 1; o < 8; o <<= 1) {
            int y = __shfl_up_sync(0xffu, x, o, 8);
            if (t >= o) x += y;
        }
        ws[t] = x;
    }
    __syncthreads();
    int excl = incl - v + (w > 0 ? ws[w - 1] : 0);
    if (i < N_NODES) g_offset[i] = excl;
    if (t == 255) g_blocksum[b] = ws[7];
}
__global__ void scan_sums() {
    int t = threadIdx.x;
    int v = (t < SCAN_BLOCKS) ? g_blocksum[t] : 0;
    int lane = t & 31, w = t >> 5;
    int incl = v;
#pragma unroll
    for (int o = 1; o < 32; o <<= 1) {
        int y = __shfl_up_sync(0xffffffffu, incl, o);
        if (lane >= o) incl += y;
    }
    __shared__ int ws[8];
    if (lane == 31) ws[w] = incl;
    __syncthreads();
    if (t < 8) {
        int x = ws[t];
#pragma unroll
        for (int o = 1; o < 8; o <<= 1) {
            int y = __shfl_up_sync(0xffu, x, o, 8);
            if (t >= o) x += y;
        }
        ws[t] = x;
    }
    __syncthreads();
    int excl = incl - v + (w > 0 ? ws[w - 1] : 0);
    if (t < SCAN_BLOCKS) g_blocksum[t] = excl;
}
__global__ void scan_add() {
    int b = blockIdx.x, t = threadIdx.x;
    int i = b * 256 + t;
    if (i >= N_NODES) return;
    int off = g_offset[i] + g_blocksum[b];
    g_offset[i] = off;
    g_cursor[i] = off;
}
__global__ void scatter_kernel(const int* __restrict__ esrc, const int* __restrict__ edst,
                               const float* __restrict__ ew) {
    int i = blockIdx.x * blockDim.x + threadIdx.x;
    if (i >= N_EDGES) return;
    int d = edst[i];
    int pos = atomicAdd(&g_cursor[d], 1);
    g_sorted_src[pos] = esrc[i];
    g_sorted_w[pos] = ew[i];
}

// ---------------- per-node max aggregation (fp16 gather table) ----------------
__global__ void agg_kernel(const float* __restrict__ Wm, const float* __restrict__ bm) {
    int gw = (blockIdx.x * blockDim.x + threadIdx.x) >> 5;
    int lane = threadIdx.x & 31;
    if (gw >= N_NODES) return;

    int start = g_offset[gw];
    int cnt = (gw + 1 < N_NODES ? g_offset[gw + 1] : N_EDGES) - start;
    float4 outv = make_float4(0.f, 0.f, 0.f, 0.f);
    if (cnt > 0) {
        float4 w4 = *(const float4*)(Wm + 256 * 128 + lane * 4);  // ww
        float4 m = make_float4(-CUDART_INF_F, -CUDART_INF_F, -CUDART_INF_F, -CUDART_INF_F);
        int e = start, end = start + cnt;
        for (; e < end; e++) {
            int s = g_sorted_src[e];
            float w = g_sorted_w[e];
            uint2 u = *(const uint2*)(g_Ps16 + (size_t)s * HID + lane * 4);
            float2 p01 = __half22float2(*(__half2*)&u.x);
            float2 p23 = __half22float2(*(__half2*)&u.y);
            m.x = fmaxf(m.x, fmaf(w, w4.x, p01.x));
            m.y = fmaxf(m.y, fmaf(w, w4.y, p01.y));
            m.z = fmaxf(m.z, fmaf(w, w4.z, p23.x));
            m.w = fmaxf(m.w, fmaf(w, w4.w, p23.y));
        }
        float4 q = *(const float4*)(g_P + (size_t)gw * PW + 128 + lane * 4);  // z@Wd
        float4 b = *(const float4*)(bm + lane * 4);
        outv.x = q.x + b.x + m.x;
        outv.y = q.y + b.y + m.y;
        outv.z = q.z + b.z + m.z;
        outv.w = q.w + b.w + m.w;
    }
    *(float4*)(g_agg + (size_t)gw * HID + lane * 4) = outv;
}

// ---------------- launch ----------------
extern "C" void kernel_launch(void* const* d_in, const int* in_sizes, int n_in,
                              void* d_out, int out_size) {
    const float* z    = (const float*)d_in[0];
    const float* ew   = (const float*)d_in[1];
    const int*   esrc = (const int*)d_in[2];
    const int*   edst = (const int*)d_in[3];
    const float* Wm   = (const float*)d_in[4];
    const float* bm   = (const float*)d_in[5];
    const float* W1   = (const float*)d_in[6];
    const float* b1   = (const float*)d_in[7];
    const float* W2   = (const float*)d_in[8];
    const float* b2   = (const float*)d_in[9];
    float* out = (float*)d_out;

    static bool attr_set = false;
    if (!attr_set) {
        cudaFuncSetAttribute(gemm_z_fused, cudaFuncAttributeMaxDynamicSharedMemorySize, SM_Z_TOTAL);
        cudaFuncSetAttribute(gemm_tail,    cudaFuncAttributeMaxDynamicSharedMemorySize, SM_T_TOTAL);
        attr_set = true;
    }

    const int NT = (N_NODES + 127) / 128;  // 391 row tiles

    zero_count_kernel<<<SCAN_BLOCKS, 256>>>();
    gemm_z_fused<<<NT, 256, SM_Z_TOTAL>>>(z, Wm, W1, N_NODES);

    hist_kernel<<<N_EDGES / 256, 256>>>(edst);
    scan_local<<<SCAN_BLOCKS, 256>>>();
    scan_sums<<<1, 256>>>();
    scan_add<<<SCAN_BLOCKS, 256>>>();
    scatter_kernel<<<N_EDGES / 256, 256>>>(esrc, edst, ew);
    agg_kernel<<<(N_NODES * 32 + 255) / 256, 256>>>(Wm, bm);

    gemm_tail<<<NT, 256, SM_T_TOTAL>>>(W1 + 128 * 128, b1, W2, b2, out, N_NODES);
}

// round 6
// speedup vs baseline: 1.1875x; 1.1875x over previous
#include <cuda_runtime.h>
#include <cuda_bf16.h>
#include <cuda_fp16.h>
#include <math_constants.h>
#include <cstdint>

#define N_NODES 50000
#define N_EDGES 800000
#define HID 128
#define PW 384   // [0:128)=z@Ws, [128:256)=z@Wd, [256:384)=z@W1a
#define SCAN_BLOCKS ((N_NODES + 255) / 256)   // 196

// ---------------- scratch ----------------
__device__ float  g_P[(size_t)N_NODES * PW];
__device__ __half g_Ps16[(size_t)N_NODES * HID];   // fp16 copy of z@Ws for edge gather
__device__ float  g_agg[(size_t)N_NODES * HID];
__device__ float  g_hidden[(size_t)N_NODES * HID];
__device__ int    g_count[N_NODES];
__device__ int    g_offset[N_NODES];
__device__ int    g_cursor[N_NODES];
__device__ int    g_blocksum[SCAN_BLOCKS];
__device__ int    g_sorted_src[N_EDGES];
__device__ float  g_sorted_w[N_EDGES];

// ---------------- mma.sync helpers (portable sm_80+ PTX) ----------------
__device__ __forceinline__ uint32_t smem_u32(const void* p) {
    uint32_t a;
    asm("{ .reg .u64 t; cvta.to.shared.u64 t, %1; cvt.u32.u64 %0, t; }" : "=r"(a) : "l"(p));
    return a;
}
__device__ __forceinline__ void ldsm_x4(uint32_t* r, uint32_t addr) {
    asm volatile("ldmatrix.sync.aligned.m8n8.x4.shared.b16 {%0,%1,%2,%3}, [%4];"
                 : "=r"(r[0]), "=r"(r[1]), "=r"(r[2]), "=r"(r[3]) : "r"(addr));
}
__device__ __forceinline__ void ldsm_x4_t(uint32_t* r, uint32_t addr) {
    asm volatile("ldmatrix.sync.aligned.m8n8.x4.trans.shared.b16 {%0,%1,%2,%3}, [%4];"
                 : "=r"(r[0]), "=r"(r[1]), "=r"(r[2]), "=r"(r[3]) : "r"(addr));
}
__device__ __forceinline__ void mma16816(float* c, const uint32_t* a, const uint32_t* b) {
    asm volatile(
        "mma.sync.aligned.m16n8k16.row.col.f32.bf16.bf16.f32 "
        "{%0,%1,%2,%3}, {%4,%5,%6,%7}, {%8,%9}, {%0,%1,%2,%3};"
        : "+f"(c[0]), "+f"(c[1]), "+f"(c[2]), "+f"(c[3])
        : "r"(a[0]), "r"(a[1]), "r"(a[2]), "r"(a[3]), "r"(b[0]), "r"(b[1]));
}
__device__ __forceinline__ uint32_t pack2(float x, float y) {
    __nv_bfloat162 h = __floats2bfloat162_rn(x, y);
    return *(uint32_t*)&h;
}
// swizzled byte offset inside a [128][128] bf16 tile (256B rows)
__device__ __forceinline__ uint32_t swz(int row, int col) {
    return (uint32_t)(row * 256 + ((((col >> 3) ^ (row & 7))) << 4) + (col & 7) * 2);
}

// smem plan (dynamic, 128 KB)
#define SM_AHI 0
#define SM_ALO 32768
#define SM_BHI 65536
#define SM_BLO 98304
#define SM_TOTAL 131072

// out[r][ocol0 + c] = f(A_tile @ B + bias + Cadd);  D = Ahi@Bhi + Ahi@Blo + Alo@Bhi
__global__ __launch_bounds__(256)
void mma_gemm(const float* __restrict__ A,
              const float* __restrict__ Bp0, const float* __restrict__ Bp1,
              const float* __restrict__ Bp2,
              const float* __restrict__ bias, const float* __restrict__ Cadd, int ldCadd,
              float* __restrict__ out, int ldOut, int M, int relu, int fp16tab)
{
    extern __shared__ char smem[];
    const uint32_t sb = smem_u32(smem);
    const int tid = threadIdx.x;
    const int wid = tid >> 5;
    const int lane = tid & 31;
    const int bm0 = blockIdx.x * 128;
    const int by = blockIdx.y;
    const float* B = (by == 0) ? Bp0 : ((by == 1) ? Bp1 : Bp2);
    const int ocol0 = by * 128;

    // ---- convert A tile: fp32 -> (hi, lo) bf16, swizzled smem ----
#pragma unroll
    for (int i = 0; i < 32; i++) {
        int p = tid + i * 256;
        int row = p >> 6;
        int col = (p & 63) * 2;
        float2 v = make_float2(0.f, 0.f);
        int gr = bm0 + row;
        if (gr < M) v = *(const float2*)(A + (size_t)gr * 128 + col);
        float hx = __bfloat162float(__float2bfloat16(v.x));
        float hy = __bfloat162float(__float2bfloat16(v.y));
        uint32_t off = swz(row, col);
        *(uint32_t*)(smem + SM_AHI + off) = pack2(hx, hy);
        *(uint32_t*)(smem + SM_ALO + off) = pack2(v.x - hx, v.y - hy);
    }
    // ---- convert B tile ----
#pragma unroll
    for (int i = 0; i < 32; i++) {
        int p = tid + i * 256;
        int row = p >> 6;
        int col = (p & 63) * 2;
        float2 v = *(const float2*)(B + (size_t)row * 128 + col);
        float hx = __bfloat162float(__float2bfloat16(v.x));
        float hy = __bfloat162float(__float2bfloat16(v.y));
        uint32_t off = swz(row, col);
        *(uint32_t*)(smem + SM_BHI + off) = pack2(hx, hy);
        *(uint32_t*)(smem + SM_BLO + off) = pack2(v.x - hx, v.y - hy);
    }
    __syncthreads();

    const int wm = wid & 1;
    const int wn = wid >> 1;
    const int sub = lane >> 3;
    const int l7 = lane & 7;
    const int radd = (sub & 1) * 8;
    const int cadd = (sub >> 1) * 8;

    float acc[4][4][4];
#pragma unroll
    for (int mt = 0; mt < 4; mt++)
#pragma unroll
        for (int nt = 0; nt < 4; nt++)
#pragma unroll
            for (int j = 0; j < 4; j++) acc[mt][nt][j] = 0.f;

#pragma unroll
    for (int ks = 0; ks < 8; ks++) {
        const int k0 = ks * 16;
        uint32_t aH[4][4], aL[4][4], bH[2][4], bL[2][4];
#pragma unroll
        for (int mt = 0; mt < 4; mt++) {
            uint32_t o = swz(wm * 64 + mt * 16 + l7 + radd, k0 + cadd);
            ldsm_x4(aH[mt], sb + SM_AHI + o);
            ldsm_x4(aL[mt], sb + SM_ALO + o);
        }
#pragma unroll
        for (int pr = 0; pr < 2; pr++) {
            uint32_t o = swz(k0 + l7 + radd, wn * 32 + pr * 16 + cadd);
            ldsm_x4_t(bH[pr], sb + SM_BHI + o);
            ldsm_x4_t(bL[pr], sb + SM_BLO + o);
        }
#pragma unroll
        for (int mt = 0; mt < 4; mt++)
#pragma unroll
            for (int nt = 0; nt < 4; nt++) {
                const uint32_t* bh = &bH[nt >> 1][(nt & 1) * 2];
                const uint32_t* bl = &bL[nt >> 1][(nt & 1) * 2];
                mma16816(acc[mt][nt], aH[mt], bh);
                mma16816(acc[mt][nt], aH[mt], bl);
                mma16816(acc[mt][nt], aL[mt], bh);
            }
    }

    // ---- epilogue ----
    const int g = lane >> 2;
    const int tg = lane & 3;
#pragma unroll
    for (int mt = 0; mt < 4; mt++) {
#pragma unroll
        for (int half = 0; half < 2; half++) {
            int r = bm0 + wm * 64 + mt * 16 + g + half * 8;
            if (r >= M) continue;
            float* orow = out + (size_t)r * ldOut + ocol0;
            const float* crow = Cadd ? (Cadd + (size_t)r * ldCadd) : nullptr;
#pragma unroll
            for (int nt = 0; nt < 4; nt++) {
                int lc = wn * 32 + nt * 8 + 2 * tg;
                float2 v;
                v.x = acc[mt][nt][half * 2 + 0];
                v.y = acc[mt][nt][half * 2 + 1];
                if (bias) { v.x += bias[lc]; v.y += bias[lc + 1]; }
                if (crow) { v.x += crow[lc]; v.y += crow[lc + 1]; }
                if (relu) { v.x = fmaxf(v.x, 0.f); v.y = fmaxf(v.y, 0.f); }
                *(float2*)(orow + lc) = v;
                if (fp16tab && by == 0) {
                    __half2 h = __floats2half2_rn(v.x, v.y);
                    *(__half2*)(g_Ps16 + (size_t)r * HID + lc) = h;
                }
            }
        }
    }
}

// ---------------- edge counting sort ----------------
__global__ void zero_count_kernel() {
    int i = blockIdx.x * blockDim.x + threadIdx.x;
    if (i < N_NODES) g_count[i] = 0;
}
__global__ void hist_kernel(const int* __restrict__ edst) {
    int i = blockIdx.x * blockDim.x + threadIdx.x;
    if (i < N_EDGES) atomicAdd(&g_count[edst[i]], 1);
}
__global__ void scan_local() {
    int b = blockIdx.x, t = threadIdx.x;
    int i = b * 256 + t;
    int v = (i < N_NODES) ? g_count[i] : 0;
    int lane = t & 31, w = t >> 5;
    int incl = v;
#pragma unroll
    for (int o = 1; o < 32; o <<= 1) {
        int y = __shfl_up_sync(0xffffffffu, incl, o);
        if (lane >= o) incl += y;
    }
    __shared__ int ws[8];
    if (lane == 31) ws[w] = incl;
    __syncthreads();
    if (t < 8) {
        int x = ws[t];
#pragma unroll
        for (int o = 1; o < 8; o <<= 1) {
            int y = __shfl_up_sync(0xffu, x, o, 8);
            if (t >= o) x += y;
        }
        ws[t] = x;
    }
    __syncthreads();
    int excl = incl - v + (w > 0 ? ws[w - 1] : 0);
    if (i < N_NODES) g_offset[i] = excl;
    if (t == 255) g_blocksum[b] = ws[7];
}
__global__ void scan_sums() {
    int t = threadIdx.x;
    int v = (t < SCAN_BLOCKS) ? g_blocksum[t] : 0;
    int lane = t & 31, w = t >> 5;
    int incl = v;
#pragma unroll
    for (int o = 1; o < 32; o <<= 1) {
        int y = __shfl_up_sync(0xffffffffu, incl, o);
        if (lane >= o) incl += y;
    }
    __shared__ int ws[8];
    if (lane == 31) ws[w] = incl;
    __syncthreads();
    if (t < 8) {
        int x = ws[t];
#pragma unroll
        for (int o = 1; o < 8; o <<= 1) {
            int y = __shfl_up_sync(0xffu, x, o, 8);
            if (t >= o) x += y;
        }
        ws[t] = x;
    }
    __syncthreads();
    int excl = incl - v + (w > 0 ? ws[w - 1] : 0);
    if (t < SCAN_BLOCKS) g_blocksum[t] = excl;
}
__global__ void scan_add() {
    int b = blockIdx.x, t = threadIdx.x;
    int i = b * 256 + t;
    if (i >= N_NODES) return;
    int off = g_offset[i] + g_blocksum[b];
    g_offset[i] = off;
    g_cursor[i] = off;
}
__global__ void scatter_kernel(const int* __restrict__ esrc, const int* __restrict__ edst,
                               const float* __restrict__ ew) {
    int i = blockIdx.x * blockDim.x + threadIdx.x;
    if (i >= N_EDGES) return;
    int d = edst[i];
    int pos = atomicAdd(&g_cursor[d], 1);
    g_sorted_src[pos] = esrc[i];
    g_sorted_w[pos] = ew[i];
}

// ---------------- per-node max aggregation (fp16 gather table) ----------------
__global__ void agg_kernel(const float* __restrict__ Wm, const float* __restrict__ bm) {
    int gw = (blockIdx.x * blockDim.x + threadIdx.x) >> 5;
    int lane = threadIdx.x & 31;
    if (gw >= N_NODES) return;

    int start = g_offset[gw];
    int cnt = (gw + 1 < N_NODES ? g_offset[gw + 1] : N_EDGES) - start;
    float4 outv = make_float4(0.f, 0.f, 0.f, 0.f);
    if (cnt > 0) {
        float4 w4 = *(const float4*)(Wm + 256 * 128 + lane * 4);  // ww
        float4 m = make_float4(-CUDART_INF_F, -CUDART_INF_F, -CUDART_INF_F, -CUDART_INF_F);
        int e = start, end = start + cnt;
        for (; e < end; e++) {
            int s = g_sorted_src[e];
            float w = g_sorted_w[e];
            uint2 u = *(const uint2*)(g_Ps16 + (size_t)s * HID + lane * 4);
            float2 p01 = __half22float2(*(__half2*)&u.x);
            float2 p23 = __half22float2(*(__half2*)&u.y);
            m.x = fmaxf(m.x, fmaf(w, w4.x, p01.x));
            m.y = fmaxf(m.y, fmaf(w, w4.y, p01.y));
            m.z = fmaxf(m.z, fmaf(w, w4.z, p23.x));
            m.w = fmaxf(m.w, fmaf(w, w4.w, p23.y));
        }
        float4 q = *(const float4*)(g_P + (size_t)gw * PW + 128 + lane * 4);  // z@Wd
        float4 b = *(const float4*)(bm + lane * 4);
        outv.x = q.x + b.x + m.x;
        outv.y = q.y + b.y + m.y;
        outv.z = q.z + b.z + m.z;
        outv.w = q.w + b.w + m.w;
    }
    *(float4*)(g_agg + (size_t)gw * HID + lane * 4) = outv;
}

// ---------------- launch ----------------
extern "C" void kernel_launch(void* const* d_in, const int* in_sizes, int n_in,
                              void* d_out, int out_size) {
    const float* z    = (const float*)d_in[0];
    const float* ew   = (const float*)d_in[1];
    const int*   esrc = (const int*)d_in[2];
    const int*   edst = (const int*)d_in[3];
    const float* Wm   = (const float*)d_in[4];
    const float* bm   = (const float*)d_in[5];
    const float* W1   = (const float*)d_in[6];
    const float* b1   = (const float*)d_in[7];
    const float* W2   = (const float*)d_in[8];
    const float* b2   = (const float*)d_in[9];
    float* out = (float*)d_out;

    float *P, *AGG, *HIDN;
    cudaGetSymbolAddress((void**)&P, g_P);
    cudaGetSymbolAddress((void**)&AGG, g_agg);
    cudaGetSymbolAddress((void**)&HIDN, g_hidden);

    static bool attr_set = false;
    if (!attr_set) {
        cudaFuncSetAttribute(mma_gemm, cudaFuncAttributeMaxDynamicSharedMemorySize, SM_TOTAL);
        attr_set = true;
    }

    const int NT = (N_NODES + 127) / 128;  // 391 row tiles

    zero_count_kernel<<<SCAN_BLOCKS, 256>>>();

    // P[:,0:128)=z@Ws (+fp16 table), [128:256)=z@Wd, [256:384)=z@W1a
    mma_gemm<<<dim3(NT, 3), 256, SM_TOTAL>>>(
        z, Wm + 128 * 128, Wm, W1, nullptr, nullptr, 0, P, PW, N_NODES, 0, 1);

    hist_kernel<<<N_EDGES / 256, 256>>>(edst);
    scan_local<<<SCAN_BLOCKS, 256>>>();
    scan_sums<<<1, 256>>>();
    scan_add<<<SCAN_BLOCKS, 256>>>();
    scatter_kernel<<<N_EDGES / 256, 256>>>(esrc, edst, ew);
    agg_kernel<<<(N_NODES * 32 + 255) / 256, 256>>>(Wm, bm);

    // hidden = relu(agg @ W1b + b1 + P[:,256:384))
    mma_gemm<<<dim3(NT, 1), 256, SM_TOTAL>>>(
        AGG, W1 + 128 * 128, nullptr, nullptr, b1, P + 256, PW, HIDN, HID, N_NODES, 1, 0);

    // out = hidden @ W2 + b2
    mma_gemm<<<dim3(NT, 1), 256, SM_TOTAL>>>(
        HIDN, W2, nullptr, nullptr, b2, nullptr, 0, out, HID, N_NODES, 0, 0);
}